// round 6
// baseline (speedup 1.0000x reference)
#include <cuda_runtime.h>
#include <math.h>

#define TOPK   64
#define NANCH  340
#define MS     28
#define NROI   128          // B(2) * TOPK(64)

typedef unsigned long long ull;

// ---------------- device scratch (no allocation allowed) ----------------
__device__ float g_box [NROI][4];
__device__ int   g_bint[NROI][4];
__device__ int   g_keep[NROI];
__device__ float g_logit[NROI][MS*MS];

// out layout (fp32): scores[128] | boxes[512] | labels[128] | masks[2*64*512*512] | keep[128]
#define OFF_SCORES 0
#define OFF_BOXES  128
#define OFF_LABELS 640
#define OFF_MASKS  768
#define OFF_KEEP   33555200

// ---------------- packed fp32x2 helpers (Blackwell FFMA2) ----------------
__device__ __forceinline__ ull pack2(float x) {
    ull r;
    asm("mov.b64 %0, {%1, %1};" : "=l"(r) : "f"(x));
    return r;
}
__device__ __forceinline__ void fma2(ull& d, ull a, ull b) {
    asm("fma.rn.f32x2 %0, %1, %2, %0;" : "+l"(d) : "l"(a), "l"(b));
}
__device__ __forceinline__ float2 unpack2(ull v) {
    float2 f;
    asm("mov.b64 {%0, %1}, %2;" : "=f"(f.x), "=f"(f.y) : "l"(v));
    return f;
}

// =======================================================================
// K1: decode + top-k (exact lax.top_k tie semantics) + NMS + small outputs
// =======================================================================
__global__ void k1_detect(const float* __restrict__ pred0,
                          const float* __restrict__ pred1,
                          const float* __restrict__ pred2,
                          const float* __restrict__ pred3,
                          float* __restrict__ out)
{
    int b   = blockIdx.x;
    int tid = threadIdx.x;

    __shared__ float sbox[NANCH][4];
    __shared__ ull skey[NANCH];
    __shared__ ull red[384];
    __shared__ int   topidx[TOPK];
    __shared__ float topsc [TOPK];
    __shared__ float kbox[TOPK][4];
    __shared__ int   keepf[TOPK];

    if (tid < NANCH) {
        int i = tid, li, H, stride;
        const float* pp;
        if      (i < 256) { li = i;       H = 16; stride = 32;  pp = pred0; }
        else if (i < 320) { li = i - 256; H = 8;  stride = 64;  pp = pred1; }
        else if (i < 336) { li = i - 320; H = 4;  stride = 128; pp = pred2; }
        else              { li = i - 336; H = 2;  stride = 256; pp = pred3; }
        int hw = H * H;
        const float* base = pp + b * 6 * hw;
        float v0 = base[li];
        float v1 = base[hw   + li];
        float v2 = base[2*hw + li];
        float v3 = base[3*hw + li];
        float v4 = base[4*hw + li];
        int y = li / H, x = li % H;
        float cx = (v0 + (float)x) * (float)stride;
        float cy = (v1 + (float)y) * (float)stride;
        float w  = expf(v2) * (float)stride;
        float h  = expf(v3) * (float)stride;
        sbox[i][0] = cx - w * 0.5f;
        sbox[i][1] = cy - h * 0.5f;
        sbox[i][2] = cx + w * 0.5f;
        sbox[i][3] = cy + h * 0.5f;
        float sc   = 1.f / (1.f + expf(-v4));
        float sval = (sc > 0.5f) ? sc : 0.f;        // where(valid, score, 0)
        skey[i] = ((ull)__float_as_uint(sval) << 32)
                | (ull)(0xFFFFFFFFu - (unsigned)i);
    }
    __syncthreads();

    for (int k = 0; k < TOPK; k++) {
        red[tid] = (tid < NANCH) ? skey[tid] : 0ULL;
        __syncthreads();
        if (tid < 128) { if (red[tid + 256] > red[tid]) red[tid] = red[tid + 256]; }
        __syncthreads();
        for (int s = 128; s > 0; s >>= 1) {
            if (tid < s) { if (red[tid + s] > red[tid]) red[tid] = red[tid + s]; }
            __syncthreads();
        }
        if (tid == 0) {
            ull best = red[0];
            int idx   = (int)(0xFFFFFFFFu - (unsigned)(best & 0xFFFFFFFFu));
            topidx[k] = idx;
            topsc [k] = __uint_as_float((unsigned)(best >> 32));
            skey[idx] = 0ULL;
        }
        __syncthreads();
    }

    if (tid < TOPK) {
        int idx = topidx[tid];
        for (int j = 0; j < 4; j++) kbox[tid][j] = sbox[idx][j];
        keepf[tid] = (topsc[tid] > 0.5f) ? 1 : 0;
    }
    __syncthreads();

    for (int i = 0; i < TOPK; i++) {
        if (tid < TOPK && tid > i && keepf[tid] && keepf[i]) {
            float ax0=kbox[i][0], ay0=kbox[i][1], ax1=kbox[i][2], ay1=kbox[i][3];
            float bx0=kbox[tid][0], by0=kbox[tid][1], bx1=kbox[tid][2], by1=kbox[tid][3];
            float aa = fmaxf(ax1-ax0,0.f)*fmaxf(ay1-ay0,0.f);
            float ab = fmaxf(bx1-bx0,0.f)*fmaxf(by1-by0,0.f);
            float ix0 = fmaxf(ax0,bx0), iy0 = fmaxf(ay0,by0);
            float ix1 = fminf(ax1,bx1), iy1 = fminf(ay1,by1);
            float inter = fmaxf(ix1-ix0,0.f)*fmaxf(iy1-iy0,0.f);
            float uni = aa + ab - inter;
            float iou = inter / fmaxf(uni, 1e-9f);
            if (iou > 0.5f) keepf[tid] = 0;
        }
        __syncthreads();
    }

    if (tid < TOPK) {
        int r  = b * TOPK + tid;
        int kp = keepf[tid];
        out[OFF_SCORES + r] = kp ? topsc[tid] : 0.f;
        for (int j = 0; j < 4; j++) out[OFF_BOXES + r*4 + j] = kbox[tid][j];
        out[OFF_LABELS + r] = 0.f;
        out[OFF_KEEP   + r] = kp ? 1.f : 0.f;
        g_keep[r] = kp;
        for (int j = 0; j < 4; j++) {
            g_box[r][j]  = kbox[tid][j];
            float c = fminf(fmaxf(kbox[tid][j], 0.f), 511.f);
            g_bint[r][j] = (int)c;
        }
    }
}

// =======================================================================
// K3 (fused ROI-align + conv): double-buffered software pipeline.
// Stage s covers input channels {2s, 2s+1}; 128 stages.
//   staging: 4-tap bilinear sample straight from feature maps (was k2) +
//            weight slice; stored as broadcast-packed float2 / plain floats.
//   compute: pure LDS.64 + FFMA2 over oc-pairs (4 pairs x 7 px per thread).
// Accumulation order per (oc,px): channel ascending, ky, kx -> bit-identical
// to the R3/R4 passing kernels.
// =======================================================================
__global__ void __launch_bounds__(256, 2)
k3_conv(const float* __restrict__ f0, const float* __restrict__ f1,
        const float* __restrict__ f2, const float* __restrict__ f3,
        const float* __restrict__ w1, const float* __restrict__ b1,
        const float* __restrict__ w2, const float* __restrict__ b2)
{
    int r = blockIdx.y;
    if (!g_keep[r]) return;
    int rt  = blockIdx.x;           // row tile: rows rt*4 .. rt*4+3
    int tid = threadIdx.x;
    int tx = tid & 15, ty = tid >> 4;
    int b  = r >> 6;

    __shared__ __align__(16) float  w_s [2][2][9][128];  // [buf][c][tap][oc]
    __shared__ __align__(16) float2 in2_s[2][2][6][30];  // [buf][c][row][col] (v,v)
    __shared__ float redbuf[16][112];

    // ---- per-thread staging descriptors (constant across stages) ----
    // input elements: e = tid (always) and e = tid+256 (if < 360)
    int   el_ok[2];     // padding-interior flag
    int   el_ci[2];     // channel-in-pair (0/1)
    int   el_row[2], el_col[2];
    int   el_x0[2], el_y0[2], el_x1[2], el_y1[2];
    float el_fx[2], el_fy[2];
    int   el_live[2];
    {
        float bx0 = g_box[r][0]*0.25f, by0 = g_box[r][1]*0.25f;
        float bx1 = g_box[r][2]*0.25f, by1 = g_box[r][3]*0.25f;
        float bw = (bx1 - bx0) / 28.f;
        float bh = (by1 - by0) / 28.f;
        #pragma unroll
        for (int j = 0; j < 2; j++) {
            int e = tid + 256*j;
            el_live[j] = (e < 360);
            if (!el_live[j]) { el_ok[j]=0; el_ci[j]=0; el_row[j]=0; el_col[j]=0;
                               el_x0[j]=el_y0[j]=el_x1[j]=el_y1[j]=0;
                               el_fx[j]=el_fy[j]=0.f; continue; }
            int ci = e / 180, pe = e - ci*180;
            int row = pe / 30, col = pe - row*30;
            el_ci[j] = ci; el_row[j] = row; el_col[j] = col;
            int gy = rt*4 + row - 1, gx = col - 1;
            int ok = (gy >= 0 && gy < 28 && gx >= 0 && gx < 28);
            el_ok[j] = ok;
            if (ok) {
                float xx = bx0 + ((float)gx + 0.5f) * bw;
                float yy = by0 + ((float)gy + 0.5f) * bh;
                xx = fminf(fmaxf(xx, 0.f), 127.f);
                yy = fminf(fmaxf(yy, 0.f), 127.f);
                int x0 = (int)floorf(xx), y0 = (int)floorf(yy);
                int x1 = min(x0 + 1, 127), y1 = min(y0 + 1, 127);
                el_fx[j] = xx - (float)x0; el_fy[j] = yy - (float)y0;
                el_x0[j] = x0; el_y0[j] = y0; el_x1[j] = x1; el_y1[j] = y1;
            } else { el_x0[j]=el_y0[j]=el_x1[j]=el_y1[j]=0; el_fx[j]=el_fy[j]=0.f; }
        }
    }
    // weight elements: e = tid + 256k, k = 0..8 (9*256 == 2304 exactly)
    int wb_idx[9];
    {
        #pragma unroll
        for (int k = 0; k < 9; k++) {
            int e = tid + 256*k;
            int c = e / 1152; int rem = e - c*1152;
            int tap = rem >> 7; int oc = rem & 127;
            wb_idx[k] = oc*2304 + c*9 + tap;     // + stage*18 at use
        }
    }

    float acc_stage_w[9];
    float a00[2], a01[2], a10[2], a11[2];

    // ---- staging: issue loads for stage s ----
    #define ISSUE_LOADS(s)                                                    \
    {                                                                         \
        _Pragma("unroll")                                                     \
        for (int k = 0; k < 9; k++)                                           \
            acc_stage_w[k] = w1[wb_idx[k] + (s)*18];                          \
        _Pragma("unroll")                                                     \
        for (int j = 0; j < 2; j++) {                                         \
            a00[j]=a01[j]=a10[j]=a11[j]=0.f;                                  \
            if (el_live[j] && el_ok[j]) {                                     \
                int ch = 2*(s) + el_ci[j];                                    \
                int l = ch >> 6, cc = ch & 63, dim = 128 >> l;                \
                const float* fp = (l==0) ? f0 : (l==1) ? f1 : (l==2) ? f2 : f3;\
                fp += (size_t)(b*64 + cc) * dim * dim;                        \
                int yA = el_y0[j] >> l, yB = el_y1[j] >> l;                   \
                int xA = el_x0[j] >> l, xB = el_x1[j] >> l;                   \
                a00[j] = fp[yA*dim + xA];                                     \
                a01[j] = fp[yA*dim + xB];                                     \
                a10[j] = fp[yB*dim + xA];                                     \
                a11[j] = fp[yB*dim + xB];                                     \
            }                                                                 \
        }                                                                     \
    }

    // ---- staging: combine + store into buffer bb ----
    #define COMMIT_LOADS(bb)                                                  \
    {                                                                         \
        _Pragma("unroll")                                                     \
        for (int k = 0; k < 9; k++) {                                         \
            int e = tid + 256*k;                                              \
            int c = e / 1152; int rem = e - c*1152;                           \
            int tap = rem >> 7; int oc = rem & 127;                           \
            w_s[bb][c][tap][oc] = acc_stage_w[k];                             \
        }                                                                     \
        _Pragma("unroll")                                                     \
        for (int j = 0; j < 2; j++) {                                         \
            if (el_live[j]) {                                                 \
                float val = 0.f;                                              \
                if (el_ok[j]) {                                               \
                    float fx = el_fx[j], fy = el_fy[j];                       \
                    val = a00[j]*(1.f-fy)*(1.f-fx) + a01[j]*(1.f-fy)*fx       \
                        + a10[j]*fy*(1.f-fx)       + a11[j]*fy*fx;            \
                }                                                             \
                in2_s[bb][el_ci[j]][el_row[j]][el_col[j]] = make_float2(val, val);\
            }                                                                 \
        }                                                                     \
    }

    ull acc[4][7];
    ull z = pack2(0.f);
    #pragma unroll
    for (int j = 0; j < 4; j++)
        #pragma unroll
        for (int p = 0; p < 7; p++) acc[j][p] = z;

    int pr[7], pc[7];
    #pragma unroll
    for (int p = 0; p < 7; p++) {
        int px = tx + 16 * p;               // 0..111 (4 rows x 28 cols)
        pr[p] = px / 28; pc[p] = px % 28;
    }
    int oc0 = ty * 8;

    // prologue
    ISSUE_LOADS(0);
    COMMIT_LOADS(0);
    __syncthreads();

    for (int it = 0; it < 128; it++) {
        int cur = it & 1;
        int hasNext = (it + 1 < 128);
        if (hasNext) ISSUE_LOADS(it + 1);

        #pragma unroll
        for (int c = 0; c < 2; c++) {
            #pragma unroll
            for (int ky = 0; ky < 3; ky++) {
                #pragma unroll
                for (int kx = 0; kx < 3; kx++) {
                    const ull* wp = (const ull*)&w_s[cur][c][ky*3+kx][oc0];
                    ull w0 = wp[0], w1p = wp[1], w2p = wp[2], w3p = wp[3];
                    #pragma unroll
                    for (int p = 0; p < 7; p++) {
                        ull bb = *(const ull*)&in2_s[cur][c][pr[p]+ky][pc[p]+kx];
                        fma2(acc[0][p], w0,  bb);
                        fma2(acc[1][p], w1p, bb);
                        fma2(acc[2][p], w2p, bb);
                        fma2(acc[3][p], w3p, bb);
                    }
                }
            }
        }
        if (hasNext) COMMIT_LOADS(cur ^ 1);
        __syncthreads();
    }

    // SiLU + 1x1 conv partials
    float lp[7];
    #pragma unroll
    for (int p = 0; p < 7; p++) lp[p] = 0.f;
    #pragma unroll
    for (int j = 0; j < 4; j++) {
        int oca = oc0 + 2*j, ocb = oc0 + 2*j + 1;
        float ba = b1[oca], bb_ = b1[ocb];
        float wa = w2[oca], wb = w2[ocb];
        #pragma unroll
        for (int p = 0; p < 7; p++) {
            float2 v = unpack2(acc[j][p]);
            float ha = v.x + ba;
            float hb = v.y + bb_;
            lp[p] += wa * (ha / (1.f + expf(-ha)));
            lp[p] += wb * (hb / (1.f + expf(-hb)));
        }
    }
    #pragma unroll
    for (int p = 0; p < 7; p++) redbuf[ty][tx + 16*p] = lp[p];
    __syncthreads();
    if (tid < 112) {
        float s = b2[0];
        #pragma unroll
        for (int t = 0; t < 16; t++) s += redbuf[t][tid];
        int row = rt*4 + tid / 28, col = tid % 28;
        g_logit[r][row*28 + col] = s;   // sign(logit) == (sigmoid > 0.5)
    }
    #undef ISSUE_LOADS
    #undef COMMIT_LOADS
}

// =======================================================================
// K4: paste -> binary masks (float 0/1). grid (512 rows, 128 rois), 128 thr
// =======================================================================
__global__ void k4_paste(float* __restrict__ out)
{
    int r = blockIdx.y;
    int y = blockIdx.x;
    int tid = threadIdx.x;
    float4* dst = (float4*)(out + OFF_MASKS + (size_t)r*262144 + (size_t)y*512);

    __shared__ float brow[28];
    float4 v = make_float4(0.f, 0.f, 0.f, 0.f);
    int kp = g_keep[r];
    if (kp) {
        int x0 = g_bint[r][0], y0 = g_bint[r][1];
        int x1 = g_bint[r][2], y1 = g_bint[r][3];
        if (y >= y0 && y <= y1) {
            int h = y1 - y0 + 1, w = x1 - x0 + 1;
            int iy = min((y - y0) * 28 / h, 27);
            if (tid < 28) brow[tid] = (g_logit[r][iy*28 + tid] > 0.f) ? 1.f : 0.f;
            __syncthreads();
            float* vv = (float*)&v;
            #pragma unroll
            for (int q = 0; q < 4; q++) {
                int x = tid * 4 + q;
                if (x >= x0 && x <= x1) {
                    int ix = min((x - x0) * 28 / w, 27);
                    vv[q] = brow[ix];
                }
            }
        }
    }
    dst[tid] = v;
}

// =======================================================================
extern "C" void kernel_launch(void* const* d_in, const int* in_sizes, int n_in,
                              void* d_out, int out_size)
{
    const float* pred0 = (const float*)d_in[0];
    const float* pred1 = (const float*)d_in[1];
    const float* pred2 = (const float*)d_in[2];
    const float* pred3 = (const float*)d_in[3];
    const float* feat0 = (const float*)d_in[4];
    const float* feat1 = (const float*)d_in[5];
    const float* feat2 = (const float*)d_in[6];
    const float* feat3 = (const float*)d_in[7];
    const float* w1    = (const float*)d_in[8];
    const float* b1    = (const float*)d_in[9];
    const float* w2    = (const float*)d_in[10];
    const float* b2    = (const float*)d_in[11];
    float* out = (float*)d_out;
    (void)in_sizes; (void)n_in; (void)out_size;

    k1_detect<<<2, 384>>>(pred0, pred1, pred2, pred3, out);
    k3_conv  <<<dim3(7, NROI), 256>>>(feat0, feat1, feat2, feat3, w1, b1, w2, b2);
    k4_paste <<<dim3(512, NROI), 128>>>(out);
}

// round 9
// speedup vs baseline: 1.5237x; 1.5237x over previous
#include <cuda_runtime.h>
#include <math.h>
#include <stdint.h>

#define TOPK   64
#define NANCH  340
#define MS     28
#define NROI   128          // B(2) * TOPK(64)

typedef unsigned long long ull;

// ---------------- device scratch (no allocation allowed) ----------------
__device__ float g_box [NROI][4];
__device__ int   g_bint[NROI][4];
__device__ int   g_keep[NROI];
__device__ int   g_list[NROI];     // compacted kept roi ids
__device__ int   g_nitems;         // 7 * nkept
__device__ float g_logit[NROI][MS*MS];
__device__ float g_roi[NROI][256][900];       // padded 30x30 per channel
__device__ float g_w1t[256*9*128];            // [(ci*9+tap)*128 + oc]

// out layout (fp32): scores[128] | boxes[512] | labels[128] | masks[2*64*512*512] | keep[128]
#define OFF_SCORES 0
#define OFF_BOXES  128
#define OFF_LABELS 640
#define OFF_MASKS  768
#define OFF_KEEP   33555200

// ---------------- packed fp32x2 helpers (Blackwell FFMA2) ----------------
__device__ __forceinline__ ull pack2(float x) {
    ull r; asm("mov.b64 %0, {%1, %1};" : "=l"(r) : "f"(x)); return r;
}
__device__ __forceinline__ void fma2(ull& d, ull a, ull b) {
    asm("fma.rn.f32x2 %0, %1, %2, %0;" : "+l"(d) : "l"(a), "l"(b));
}
__device__ __forceinline__ float2 unpack2(ull v) {
    float2 f; asm("mov.b64 {%0, %1}, %2;" : "=f"(f.x), "=f"(f.y) : "l"(v)); return f;
}
__device__ __forceinline__ uint32_t s2u(const void* p) {
    return (uint32_t)__cvta_generic_to_shared(p);
}
__device__ __forceinline__ void cpasync16(uint32_t smem, const void* g) {
    asm volatile("cp.async.ca.shared.global [%0], [%1], 16;" :: "r"(smem), "l"(g));
}
#define CP_COMMIT()  asm volatile("cp.async.commit_group;" ::: "memory")
#define CP_WAIT1()   asm volatile("cp.async.wait_group 1;" ::: "memory")
#define CP_WAIT0()   asm volatile("cp.async.wait_group 0;" ::: "memory")

// =======================================================================
// K0: transpose conv1 weights -> g_w1t[(ci*9+tap)*128 + oc]
// =======================================================================
__global__ void k0_wt(const float* __restrict__ w1)
{
    int idx = blockIdx.x * 256 + threadIdx.x;
    if (idx < 256*9*128) {
        int oc = idx & 127;
        int ct = idx >> 7;          // ci*9+tap
        int ci = ct / 9, tap = ct - ci*9;
        g_w1t[idx] = w1[(size_t)oc*2304 + ci*9 + tap];
    }
}

// =======================================================================
// K1: decode + warp-shuffle top-k + NMS + outputs + compaction (1 block)
// =======================================================================
__global__ void k1_detect(const float* __restrict__ pred0,
                          const float* __restrict__ pred1,
                          const float* __restrict__ pred2,
                          const float* __restrict__ pred3,
                          float* __restrict__ out)
{
    int tid  = threadIdx.x;           // 384
    int wid  = tid >> 5, lane = tid & 31;

    __shared__ float sbox[2][NANCH][4];
    __shared__ ull   skey[2][NANCH];
    __shared__ int   topidx[2][TOPK];
    __shared__ float topsc [2][TOPK];
    __shared__ float kbox[2][TOPK][4];
    __shared__ int   keepf[2][TOPK];
    __shared__ int   woff[4];

    const float* preds[4] = {pred0, pred1, pred2, pred3};

    for (int a = tid; a < 2*NANCH; a += 384) {
        int b = a / NANCH, i = a - b*NANCH;
        int li, lv, H, stride;
        if      (i < 256) { li = i;       lv = 0; H = 16; stride = 32;  }
        else if (i < 320) { li = i - 256; lv = 1; H = 8;  stride = 64;  }
        else if (i < 336) { li = i - 320; lv = 2; H = 4;  stride = 128; }
        else              { li = i - 336; lv = 3; H = 2;  stride = 256; }
        int hw = H * H;
        const float* base = preds[lv] + b * 6 * hw;
        float v0 = base[li];
        float v1 = base[hw   + li];
        float v2 = base[2*hw + li];
        float v3 = base[3*hw + li];
        float v4 = base[4*hw + li];
        int y = li / H, x = li % H;
        float cx = (v0 + (float)x) * (float)stride;
        float cy = (v1 + (float)y) * (float)stride;
        float w  = expf(v2) * (float)stride;
        float h  = expf(v3) * (float)stride;
        sbox[b][i][0] = cx - w * 0.5f;
        sbox[b][i][1] = cy - h * 0.5f;
        sbox[b][i][2] = cx + w * 0.5f;
        sbox[b][i][3] = cy + h * 0.5f;
        float sc   = 1.f / (1.f + expf(-v4));
        float sval = (sc > 0.5f) ? sc : 0.f;
        skey[b][i] = ((ull)__float_as_uint(sval) << 32)
                   | (ull)(0xFFFFFFFFu - (unsigned)i);
    }
    __syncthreads();

    // warp 0 -> batch 0, warp 1 -> batch 1: 64 rounds, shfl reductions
    if (wid < 2) {
        int b = wid;
        for (int k = 0; k < TOPK; k++) {
            ull m = 0ULL;
            for (int i = lane; i < NANCH; i += 32) {
                ull v = skey[b][i]; if (v > m) m = v;
            }
            #pragma unroll
            for (int o = 16; o > 0; o >>= 1) {
                ull v = __shfl_down_sync(0xFFFFFFFFu, m, o);
                if (v > m) m = v;
            }
            m = __shfl_sync(0xFFFFFFFFu, m, 0);
            if (lane == 0) {
                int idx = (int)(0xFFFFFFFFu - (unsigned)(m & 0xFFFFFFFFu));
                topidx[b][k] = idx;
                topsc [b][k] = __uint_as_float((unsigned)(m >> 32));
                skey[b][idx] = 0ULL;
            }
            __syncwarp();
        }
    }
    __syncthreads();

    if (tid < 128) {
        int b = tid >> 6, j = tid & 63;
        int idx = topidx[b][j];
        for (int q = 0; q < 4; q++) kbox[b][j][q] = sbox[b][idx][q];
        keepf[b][j] = (topsc[b][j] > 0.5f) ? 1 : 0;
    }
    __syncthreads();

    for (int i = 0; i < TOPK; i++) {
        if (tid < 128) {
            int b = tid >> 6, j = tid & 63;
            if (j > i && keepf[b][j] && keepf[b][i]) {
                float ax0=kbox[b][i][0], ay0=kbox[b][i][1], ax1=kbox[b][i][2], ay1=kbox[b][i][3];
                float bx0=kbox[b][j][0], by0=kbox[b][j][1], bx1=kbox[b][j][2], by1=kbox[b][j][3];
                float aa = fmaxf(ax1-ax0,0.f)*fmaxf(ay1-ay0,0.f);
                float ab = fmaxf(bx1-bx0,0.f)*fmaxf(by1-by0,0.f);
                float ix0 = fmaxf(ax0,bx0), iy0 = fmaxf(ay0,by0);
                float ix1 = fminf(ax1,bx1), iy1 = fminf(ay1,by1);
                float inter = fmaxf(ix1-ix0,0.f)*fmaxf(iy1-iy0,0.f);
                float uni = aa + ab - inter;
                float iou = inter / fmaxf(uni, 1e-9f);
                if (iou > 0.5f) keepf[b][j] = 0;
            }
        }
        __syncthreads();
    }

    if (tid < 128) {
        int b = tid >> 6, j = tid & 63;
        int r = tid;
        int kp = keepf[b][j];
        out[OFF_SCORES + r] = kp ? topsc[b][j] : 0.f;
        for (int q = 0; q < 4; q++) out[OFF_BOXES + r*4 + q] = kbox[b][j][q];
        out[OFF_LABELS + r] = 0.f;
        out[OFF_KEEP   + r] = kp ? 1.f : 0.f;
        g_keep[r] = kp;
        for (int q = 0; q < 4; q++) {
            g_box[r][q] = kbox[b][j][q];
            float c = fminf(fmaxf(kbox[b][j][q], 0.f), 511.f);
            g_bint[r][q] = (int)c;
        }
    }
    __syncthreads();

    // compaction of kept rois (tids 0..127 = warps 0..3)
    if (tid < 128) {
        int kp = keepf[tid>>6][tid&63];
        unsigned ball = __ballot_sync(0xFFFFFFFFu, kp);
        if (lane == 0) woff[wid] = __popc(ball);
    }
    __syncthreads();
    if (tid == 0) {
        int s = 0;
        for (int w = 0; w < 4; w++) { int t = woff[w]; woff[w] = s; s += t; }
        g_nitems = 7 * s;
    }
    __syncthreads();
    if (tid < 128) {
        int kp = keepf[tid>>6][tid&63];
        unsigned ball = __ballot_sync(0xFFFFFFFFu, kp);
        int pre = __popc(ball & ((1u << lane) - 1u));
        if (kp) g_list[woff[wid] + pre] = tid;
    }
}

// =======================================================================
// K2: ROI-align into padded scratch
// =======================================================================
__global__ void k2_sample(const float* __restrict__ f0,
                          const float* __restrict__ f1,
                          const float* __restrict__ f2,
                          const float* __restrict__ f3)
{
    int r = blockIdx.y;
    if (!g_keep[r]) return;
    int b = r >> 6;
    float bx0 = g_box[r][0]*0.25f, by0 = g_box[r][1]*0.25f;
    float bx1 = g_box[r][2]*0.25f, by1 = g_box[r][3]*0.25f;
    float bw = (bx1 - bx0) / 28.f;
    float bh = (by1 - by0) / 28.f;
    const float* feats[4] = {f0, f1, f2, f3};
    int cbase = blockIdx.x * 32;

    for (int e = threadIdx.x; e < 32*900; e += blockDim.x) {
        int cl = e / 900; int pe = e - cl*900;
        int py = pe / 30; int px = pe - py*30;
        int c  = cbase + cl;
        float val = 0.f;
        if (py >= 1 && py <= 28 && px >= 1 && px <= 28) {
            int gx = px - 1, gy = py - 1;
            float xx = bx0 + ((float)gx + 0.5f) * bw;
            float yy = by0 + ((float)gy + 0.5f) * bh;
            xx = fminf(fmaxf(xx, 0.f), 127.f);
            yy = fminf(fmaxf(yy, 0.f), 127.f);
            int x0 = (int)floorf(xx), y0 = (int)floorf(yy);
            int x1 = min(x0 + 1, 127), y1 = min(y0 + 1, 127);
            float fx = xx - (float)x0, fy = yy - (float)y0;
            int l = c >> 6, cc = c & 63, dim = 128 >> l;
            const float* fp = feats[l] + (size_t)(b*64 + cc) * dim * dim;
            float v00 = fp[(y0>>l)*dim + (x0>>l)];
            float v01 = fp[(y0>>l)*dim + (x1>>l)];
            float v10 = fp[(y1>>l)*dim + (x0>>l)];
            float v11 = fp[(y1>>l)*dim + (x1>>l)];
            val = v00*(1.f-fy)*(1.f-fx) + v01*(1.f-fy)*fx
                + v10*fy*(1.f-fx)       + v11*fy*fx;
        }
        g_roi[r][c][pe] = val;
    }
}

// =======================================================================
// K3: conv1(3x3,256->128)+SiLU fused with conv2(1x1,128->1) -> logits.
// Dense item remap (kept rois only), cp.async double-buffered weights,
// register-prefetched pre-packed inputs. 128 stages of 2 input channels.
// Accumulation order per (oc,px): ci ascending, ky, kx -> bit-identical
// to the R3/R4 passing kernels.
// =======================================================================
__global__ void __launch_bounds__(256, 2)
k3_conv(const float* __restrict__ b1, const float* __restrict__ w2,
        const float* __restrict__ b2)
{
    int item = blockIdx.x;
    if (item >= g_nitems) return;
    int kidx = item / 7, rt = item - kidx*7;
    int r = g_list[kidx];

    int tid = threadIdx.x;
    int tx = tid & 15, ty = tid >> 4;

    __shared__ __align__(16) float  w_s[2][2304];     // [buf][(c*9+tap)*128+oc]
    __shared__ __align__(16) float2 in2_s[2][2][180]; // [buf][c][row*30+col], (v,v)
    __shared__ float redbuf[16][112];

    // input-prefetch descriptors: 360 elems/stage; e = tid, and tid+256 if <360
    int en = (tid < 104) ? 2 : 1;
    int ec[2], er[2];
    ec[0] = tid / 180;           er[0] = tid - ec[0]*180;
    { int e1 = tid + 256;  ec[1] = e1 / 180;  er[1] = e1 - ec[1]*180; }
    const float* roi_base = &g_roi[r][0][0];
    int rowoff = rt * 120;      // (rt*4)*30

    uint32_t wdst[2] = { s2u(&w_s[0][0]), s2u(&w_s[1][0]) };
    float pin[2];

    // issue loads for stage s into buffer s&1
    // FIX (R8): per-stage weight block is 2 ci * 9 taps * 128 oc = 2304
    // floats, so the stage stride is s*2304 (was wrongly s*1152, which
    // paired channels {s,s+1} weights with channels {2s,2s+1} inputs).
    #define PREFETCH(s)                                                       \
    {                                                                         \
        const float* wsrc = g_w1t + (size_t)(s)*2304;                         \
        uint32_t wd = wdst[(s) & 1];                                          \
        for (int i = tid; i < 576; i += 256)                                  \
            cpasync16(wd + i*16, wsrc + i*4);                                 \
        CP_COMMIT();                                                          \
        _Pragma("unroll")                                                     \
        for (int j = 0; j < 2; j++)                                           \
            if (j < en)                                                       \
                pin[j] = roi_base[(size_t)(2*(s) + ec[j])*900 + rowoff + er[j]];\
    }
    #define COMMITIN(s)                                                       \
    {                                                                         \
        _Pragma("unroll")                                                     \
        for (int j = 0; j < 2; j++)                                           \
            if (j < en)                                                       \
                in2_s[(s)&1][ec[j]][er[j]] = make_float2(pin[j], pin[j]);     \
    }

    ull acc[4][7];
    ull z = pack2(0.f);
    #pragma unroll
    for (int j = 0; j < 4; j++)
        #pragma unroll
        for (int p = 0; p < 7; p++) acc[j][p] = z;

    int pr[7], pc[7];
    #pragma unroll
    for (int p = 0; p < 7; p++) {
        int px = tx + 16 * p;          // 0..111 (4 rows x 28 cols)
        pr[p] = px / 28; pc[p] = px % 28;
    }
    int oc0 = ty * 8;

    // prologue
    PREFETCH(0);
    COMMITIN(0);

    for (int it = 0; it < 128; it++) {
        int cur = it & 1;
        if (it + 1 < 128) { PREFETCH(it + 1); CP_WAIT1(); }
        else              { CP_WAIT0(); }
        __syncthreads();                       // w_s[cur] + in2_s[cur] visible

        const float* wbuf = &w_s[cur][0];
        #pragma unroll
        for (int c = 0; c < 2; c++) {
            #pragma unroll
            for (int ky = 0; ky < 3; ky++) {
                #pragma unroll
                for (int kx = 0; kx < 3; kx++) {
                    const ull* wp = (const ull*)(wbuf + (c*9 + ky*3 + kx)*128 + oc0);
                    ull w0 = wp[0], w1p = wp[1], w2p = wp[2], w3p = wp[3];
                    #pragma unroll
                    for (int p = 0; p < 7; p++) {
                        ull bb = *(const ull*)&in2_s[cur][c][(pr[p]+ky)*30 + pc[p]+kx];
                        fma2(acc[0][p], w0,  bb);
                        fma2(acc[1][p], w1p, bb);
                        fma2(acc[2][p], w2p, bb);
                        fma2(acc[3][p], w3p, bb);
                    }
                }
            }
        }
        __syncthreads();                       // done reading cur buffers
        if (it + 1 < 128) COMMITIN(it + 1);    // fill in2_s[(it+1)&1]
    }
    #undef PREFETCH
    #undef COMMITIN

    // SiLU + 1x1 conv partials
    float lp[7];
    #pragma unroll
    for (int p = 0; p < 7; p++) lp[p] = 0.f;
    #pragma unroll
    for (int j = 0; j < 4; j++) {
        int oca = oc0 + 2*j, ocb = oc0 + 2*j + 1;
        float ba = b1[oca], bb_ = b1[ocb];
        float wa = w2[oca], wb = w2[ocb];
        #pragma unroll
        for (int p = 0; p < 7; p++) {
            float2 v = unpack2(acc[j][p]);
            float ha = v.x + ba;
            float hb = v.y + bb_;
            lp[p] += wa * (ha / (1.f + expf(-ha)));
            lp[p] += wb * (hb / (1.f + expf(-hb)));
        }
    }
    #pragma unroll
    for (int p = 0; p < 7; p++) redbuf[ty][tx + 16*p] = lp[p];
    __syncthreads();
    if (tid < 112) {
        float s = b2[0];
        #pragma unroll
        for (int t = 0; t < 16; t++) s += redbuf[t][tid];
        int row = rt*4 + tid / 28, col = tid % 28;
        g_logit[r][row*28 + col] = s;   // sign(logit) == (sigmoid > 0.5)
    }
}

// =======================================================================
// K4: paste -> binary masks (float 0/1). grid (512 rows, 128 rois), 128 thr
// =======================================================================
__global__ void k4_paste(float* __restrict__ out)
{
    int r = blockIdx.y;
    int y = blockIdx.x;
    int tid = threadIdx.x;
    float4* dst = (float4*)(out + OFF_MASKS + (size_t)r*262144 + (size_t)y*512);

    __shared__ float brow[28];
    float4 v = make_float4(0.f, 0.f, 0.f, 0.f);
    int kp = g_keep[r];
    if (kp) {
        int x0 = g_bint[r][0], y0 = g_bint[r][1];
        int x1 = g_bint[r][2], y1 = g_bint[r][3];
        if (y >= y0 && y <= y1) {
            int h = y1 - y0 + 1, w = x1 - x0 + 1;
            int iy = min((y - y0) * 28 / h, 27);
            if (tid < 28) brow[tid] = (g_logit[r][iy*28 + tid] > 0.f) ? 1.f : 0.f;
            __syncthreads();
            float* vv = (float*)&v;
            #pragma unroll
            for (int q = 0; q < 4; q++) {
                int x = tid * 4 + q;
                if (x >= x0 && x <= x1) {
                    int ix = min((x - x0) * 28 / w, 27);
                    vv[q] = brow[ix];
                }
            }
        }
    }
    dst[tid] = v;
}

// =======================================================================
extern "C" void kernel_launch(void* const* d_in, const int* in_sizes, int n_in,
                              void* d_out, int out_size)
{
    const float* pred0 = (const float*)d_in[0];
    const float* pred1 = (const float*)d_in[1];
    const float* pred2 = (const float*)d_in[2];
    const float* pred3 = (const float*)d_in[3];
    const float* feat0 = (const float*)d_in[4];
    const float* feat1 = (const float*)d_in[5];
    const float* feat2 = (const float*)d_in[6];
    const float* feat3 = (const float*)d_in[7];
    const float* w1    = (const float*)d_in[8];
    const float* b1    = (const float*)d_in[9];
    const float* w2    = (const float*)d_in[10];
    const float* b2    = (const float*)d_in[11];
    float* out = (float*)d_out;
    (void)in_sizes; (void)n_in; (void)out_size;

    k0_wt    <<<1152, 256>>>(w1);
    k1_detect<<<1, 384>>>(pred0, pred1, pred2, pred3, out);
    k2_sample<<<dim3(8, NROI), 256>>>(feat0, feat1, feat2, feat3);
    k3_conv  <<<7 * NROI, 256>>>(b1, w2, b2);
    k4_paste <<<dim3(512, NROI), 128>>>(out);
}

// round 10
// speedup vs baseline: 1.8766x; 1.2316x over previous
#include <cuda_runtime.h>
#include <math.h>
#include <stdint.h>

#define TOPK   64
#define NANCH  340
#define MS     28
#define NROI   128          // B(2) * TOPK(64)

typedef unsigned long long ull;

// ---------------- device scratch (no allocation allowed) ----------------
__device__ float g_box [NROI][4];
__device__ int   g_bint[NROI][4];
__device__ int   g_keep[NROI];
__device__ int   g_list[NROI];     // compacted kept roi ids
__device__ int   g_nitems;         // 7 * nkept
__device__ float g_logit[NROI][MS*MS];
__device__ float g_roi[NROI][256][900];       // padded 30x30 per channel
__device__ float g_w1t[256*9*128];            // [(ci*9+tap)*128 + oc]

// out layout (fp32): scores[128] | boxes[512] | labels[128] | masks[2*64*512*512] | keep[128]
#define OFF_SCORES 0
#define OFF_BOXES  128
#define OFF_LABELS 640
#define OFF_MASKS  768
#define OFF_KEEP   33555200

// ---------------- packed fp32x2 helpers (Blackwell FFMA2) ----------------
__device__ __forceinline__ ull pack2(float x) {
    ull r; asm("mov.b64 %0, {%1, %1};" : "=l"(r) : "f"(x)); return r;
}
__device__ __forceinline__ void fma2(ull& d, ull a, ull b) {
    asm("fma.rn.f32x2 %0, %1, %2, %0;" : "+l"(d) : "l"(a), "l"(b));
}
__device__ __forceinline__ float2 unpack2(ull v) {
    float2 f; asm("mov.b64 {%0, %1}, %2;" : "=f"(f.x), "=f"(f.y) : "l"(v)); return f;
}
__device__ __forceinline__ uint32_t s2u(const void* p) {
    return (uint32_t)__cvta_generic_to_shared(p);
}
__device__ __forceinline__ void cpasync16(uint32_t smem, const void* g) {
    asm volatile("cp.async.ca.shared.global [%0], [%1], 16;" :: "r"(smem), "l"(g));
}
#define CP_COMMIT()  asm volatile("cp.async.commit_group;" ::: "memory")
#define CP_WAIT1()   asm volatile("cp.async.wait_group 1;" ::: "memory")
#define CP_WAIT0()   asm volatile("cp.async.wait_group 0;" ::: "memory")

// =======================================================================
// K0: transpose conv1 weights -> g_w1t[(ci*9+tap)*128 + oc]
// =======================================================================
__global__ void k0_wt(const float* __restrict__ w1)
{
    int idx = blockIdx.x * 256 + threadIdx.x;
    if (idx < 256*9*128) {
        int oc = idx & 127;
        int ct = idx >> 7;          // ci*9+tap
        int ci = ct / 9, tap = ct - ci*9;
        g_w1t[idx] = w1[(size_t)oc*2304 + ci*9 + tap];
    }
}

// =======================================================================
// K1: decode + warp-shuffle top-k + NMS + outputs + compaction (1 block)
// =======================================================================
__global__ void k1_detect(const float* __restrict__ pred0,
                          const float* __restrict__ pred1,
                          const float* __restrict__ pred2,
                          const float* __restrict__ pred3,
                          float* __restrict__ out)
{
    int tid  = threadIdx.x;           // 384
    int wid  = tid >> 5, lane = tid & 31;

    __shared__ float sbox[2][NANCH][4];
    __shared__ ull   skey[2][NANCH];
    __shared__ int   topidx[2][TOPK];
    __shared__ float topsc [2][TOPK];
    __shared__ float kbox[2][TOPK][4];
    __shared__ int   keepf[2][TOPK];
    __shared__ int   woff[4];

    const float* preds[4] = {pred0, pred1, pred2, pred3};

    for (int a = tid; a < 2*NANCH; a += 384) {
        int b = a / NANCH, i = a - b*NANCH;
        int li, lv, H, stride;
        if      (i < 256) { li = i;       lv = 0; H = 16; stride = 32;  }
        else if (i < 320) { li = i - 256; lv = 1; H = 8;  stride = 64;  }
        else if (i < 336) { li = i - 320; lv = 2; H = 4;  stride = 128; }
        else              { li = i - 336; lv = 3; H = 2;  stride = 256; }
        int hw = H * H;
        const float* base = preds[lv] + b * 6 * hw;
        float v0 = base[li];
        float v1 = base[hw   + li];
        float v2 = base[2*hw + li];
        float v3 = base[3*hw + li];
        float v4 = base[4*hw + li];
        int y = li / H, x = li % H;
        float cx = (v0 + (float)x) * (float)stride;
        float cy = (v1 + (float)y) * (float)stride;
        float w  = expf(v2) * (float)stride;
        float h  = expf(v3) * (float)stride;
        sbox[b][i][0] = cx - w * 0.5f;
        sbox[b][i][1] = cy - h * 0.5f;
        sbox[b][i][2] = cx + w * 0.5f;
        sbox[b][i][3] = cy + h * 0.5f;
        float sc   = 1.f / (1.f + expf(-v4));
        float sval = (sc > 0.5f) ? sc : 0.f;
        skey[b][i] = ((ull)__float_as_uint(sval) << 32)
                   | (ull)(0xFFFFFFFFu - (unsigned)i);
    }
    __syncthreads();

    // warp 0 -> batch 0, warp 1 -> batch 1: 64 rounds, shfl reductions
    if (wid < 2) {
        int b = wid;
        for (int k = 0; k < TOPK; k++) {
            ull m = 0ULL;
            for (int i = lane; i < NANCH; i += 32) {
                ull v = skey[b][i]; if (v > m) m = v;
            }
            #pragma unroll
            for (int o = 16; o > 0; o >>= 1) {
                ull v = __shfl_down_sync(0xFFFFFFFFu, m, o);
                if (v > m) m = v;
            }
            m = __shfl_sync(0xFFFFFFFFu, m, 0);
            if (lane == 0) {
                int idx = (int)(0xFFFFFFFFu - (unsigned)(m & 0xFFFFFFFFu));
                topidx[b][k] = idx;
                topsc [b][k] = __uint_as_float((unsigned)(m >> 32));
                skey[b][idx] = 0ULL;
            }
            __syncwarp();
        }
    }
    __syncthreads();

    if (tid < 128) {
        int b = tid >> 6, j = tid & 63;
        int idx = topidx[b][j];
        for (int q = 0; q < 4; q++) kbox[b][j][q] = sbox[b][idx][q];
        keepf[b][j] = (topsc[b][j] > 0.5f) ? 1 : 0;
    }
    __syncthreads();

    for (int i = 0; i < TOPK; i++) {
        if (tid < 128) {
            int b = tid >> 6, j = tid & 63;
            if (j > i && keepf[b][j] && keepf[b][i]) {
                float ax0=kbox[b][i][0], ay0=kbox[b][i][1], ax1=kbox[b][i][2], ay1=kbox[b][i][3];
                float bx0=kbox[b][j][0], by0=kbox[b][j][1], bx1=kbox[b][j][2], by1=kbox[b][j][3];
                float aa = fmaxf(ax1-ax0,0.f)*fmaxf(ay1-ay0,0.f);
                float ab = fmaxf(bx1-bx0,0.f)*fmaxf(by1-by0,0.f);
                float ix0 = fmaxf(ax0,bx0), iy0 = fmaxf(ay0,by0);
                float ix1 = fminf(ax1,bx1), iy1 = fminf(ay1,by1);
                float inter = fmaxf(ix1-ix0,0.f)*fmaxf(iy1-iy0,0.f);
                float uni = aa + ab - inter;
                float iou = inter / fmaxf(uni, 1e-9f);
                if (iou > 0.5f) keepf[b][j] = 0;
            }
        }
        __syncthreads();
    }

    if (tid < 128) {
        int b = tid >> 6, j = tid & 63;
        int r = tid;
        int kp = keepf[b][j];
        out[OFF_SCORES + r] = kp ? topsc[b][j] : 0.f;
        for (int q = 0; q < 4; q++) out[OFF_BOXES + r*4 + q] = kbox[b][j][q];
        out[OFF_LABELS + r] = 0.f;
        out[OFF_KEEP   + r] = kp ? 1.f : 0.f;
        g_keep[r] = kp;
        for (int q = 0; q < 4; q++) {
            g_box[r][q] = kbox[b][j][q];
            float c = fminf(fmaxf(kbox[b][j][q], 0.f), 511.f);
            g_bint[r][q] = (int)c;
        }
    }
    __syncthreads();

    // compaction of kept rois (tids 0..127 = warps 0..3)
    if (tid < 128) {
        int kp = keepf[tid>>6][tid&63];
        unsigned ball = __ballot_sync(0xFFFFFFFFu, kp);
        if (lane == 0) woff[wid] = __popc(ball);
    }
    __syncthreads();
    if (tid == 0) {
        int s = 0;
        for (int w = 0; w < 4; w++) { int t = woff[w]; woff[w] = s; s += t; }
        g_nitems = 7 * s;
    }
    __syncthreads();
    if (tid < 128) {
        int kp = keepf[tid>>6][tid&63];
        unsigned ball = __ballot_sync(0xFFFFFFFFu, kp);
        int pre = __popc(ball & ((1u << lane) - 1u));
        if (kp) g_list[woff[wid] + pre] = tid;
    }
}

// =======================================================================
// K2: ROI-align into padded scratch
// =======================================================================
__global__ void k2_sample(const float* __restrict__ f0,
                          const float* __restrict__ f1,
                          const float* __restrict__ f2,
                          const float* __restrict__ f3)
{
    int r = blockIdx.y;
    if (!g_keep[r]) return;
    int b = r >> 6;
    float bx0 = g_box[r][0]*0.25f, by0 = g_box[r][1]*0.25f;
    float bx1 = g_box[r][2]*0.25f, by1 = g_box[r][3]*0.25f;
    float bw = (bx1 - bx0) / 28.f;
    float bh = (by1 - by0) / 28.f;
    const float* feats[4] = {f0, f1, f2, f3};
    int cbase = blockIdx.x * 32;

    for (int e = threadIdx.x; e < 32*900; e += blockDim.x) {
        int cl = e / 900; int pe = e - cl*900;
        int py = pe / 30; int px = pe - py*30;
        int c  = cbase + cl;
        float val = 0.f;
        if (py >= 1 && py <= 28 && px >= 1 && px <= 28) {
            int gx = px - 1, gy = py - 1;
            float xx = bx0 + ((float)gx + 0.5f) * bw;
            float yy = by0 + ((float)gy + 0.5f) * bh;
            xx = fminf(fmaxf(xx, 0.f), 127.f);
            yy = fminf(fmaxf(yy, 0.f), 127.f);
            int x0 = (int)floorf(xx), y0 = (int)floorf(yy);
            int x1 = min(x0 + 1, 127), y1 = min(y0 + 1, 127);
            float fx = xx - (float)x0, fy = yy - (float)y0;
            int l = c >> 6, cc = c & 63, dim = 128 >> l;
            const float* fp = feats[l] + (size_t)(b*64 + cc) * dim * dim;
            float v00 = fp[(y0>>l)*dim + (x0>>l)];
            float v01 = fp[(y0>>l)*dim + (x1>>l)];
            float v10 = fp[(y1>>l)*dim + (x0>>l)];
            float v11 = fp[(y1>>l)*dim + (x1>>l)];
            val = v00*(1.f-fy)*(1.f-fx) + v01*(1.f-fy)*fx
                + v10*fy*(1.f-fx)       + v11*fy*fx;
        }
        g_roi[r][c][pe] = val;
    }
}

// =======================================================================
// K3: conv1(3x3,256->128)+SiLU fused with conv2(1x1,128->1) -> logits.
// Dense item remap, cp.async double-buffered weights, register-prefetched
// inputs. Pixel tile stored as PLAIN floats (halves pixel LDS bytes vs the
// R8 (v,v)-packed tile); the broadcast pair is built with mov.b64 {v,v}
// on the idle ALU pipe. Weights loaded as explicit 16B LDS.128.
// Accumulation order per (oc,px): ci ascending, ky, kx -> bit-identical.
// =======================================================================
__global__ void __launch_bounds__(256, 2)
k3_conv(const float* __restrict__ b1, const float* __restrict__ w2,
        const float* __restrict__ b2)
{
    int item = blockIdx.x;
    if (item >= g_nitems) return;
    int kidx = item / 7, rt = item - kidx*7;
    int r = g_list[kidx];

    int tid = threadIdx.x;
    int tx = tid & 15, ty = tid >> 4;

    __shared__ __align__(16) float w_s[2][2304];   // [buf][(c*9+tap)*128+oc]
    __shared__ __align__(16) float in_s[2][2][180];// [buf][c][row*30+col]
    __shared__ float redbuf[16][112];

    // input-prefetch descriptors: 360 elems/stage; e = tid, and tid+256 if <360
    int en = (tid < 104) ? 2 : 1;
    int ec[2], er[2];
    ec[0] = tid / 180;           er[0] = tid - ec[0]*180;
    { int e1 = tid + 256;  ec[1] = e1 / 180;  er[1] = e1 - ec[1]*180; }
    const float* roi_base = &g_roi[r][0][0];
    int rowoff = rt * 120;      // (rt*4)*30

    uint32_t wdst[2] = { s2u(&w_s[0][0]), s2u(&w_s[1][0]) };
    float pin[2];

    // per-stage weight block: 2 ci * 9 taps * 128 oc = 2304 floats
    #define PREFETCH(s)                                                       \
    {                                                                         \
        const float* wsrc = g_w1t + (size_t)(s)*2304;                         \
        uint32_t wd = wdst[(s) & 1];                                          \
        for (int i = tid; i < 576; i += 256)                                  \
            cpasync16(wd + i*16, wsrc + i*4);                                 \
        CP_COMMIT();                                                          \
        _Pragma("unroll")                                                     \
        for (int j = 0; j < 2; j++)                                           \
            if (j < en)                                                       \
                pin[j] = roi_base[(size_t)(2*(s) + ec[j])*900 + rowoff + er[j]];\
    }
    #define COMMITIN(s)                                                       \
    {                                                                         \
        _Pragma("unroll")                                                     \
        for (int j = 0; j < 2; j++)                                           \
            if (j < en)                                                       \
                in_s[(s)&1][ec[j]][er[j]] = pin[j];                           \
    }

    ull acc[4][7];
    ull z = pack2(0.f);
    #pragma unroll
    for (int j = 0; j < 4; j++)
        #pragma unroll
        for (int p = 0; p < 7; p++) acc[j][p] = z;

    int pr[7], pc[7];
    #pragma unroll
    for (int p = 0; p < 7; p++) {
        int px = tx + 16 * p;          // 0..111 (4 rows x 28 cols)
        pr[p] = px / 28; pc[p] = px % 28;
    }
    int oc0 = ty * 8;

    // prologue
    PREFETCH(0);
    COMMITIN(0);

    for (int it = 0; it < 128; it++) {
        int cur = it & 1;
        if (it + 1 < 128) { PREFETCH(it + 1); CP_WAIT1(); }
        else              { CP_WAIT0(); }
        __syncthreads();                       // w_s[cur] + in_s[cur] visible

        const float* wbuf = &w_s[cur][0];
        #pragma unroll
        for (int c = 0; c < 2; c++) {
            #pragma unroll
            for (int ky = 0; ky < 3; ky++) {
                #pragma unroll
                for (int kx = 0; kx < 3; kx++) {
                    const ulonglong2* wp =
                        (const ulonglong2*)(wbuf + (c*9 + ky*3 + kx)*128 + oc0);
                    ulonglong2 wq0 = wp[0], wq1 = wp[1];   // LDS.128 x2
                    const float* ib = &in_s[cur][c][ky*30 + kx];
                    #pragma unroll
                    for (int p = 0; p < 7; p++) {
                        ull bb = pack2(ib[pr[p]*30 + pc[p]]);
                        fma2(acc[0][p], wq0.x, bb);
                        fma2(acc[1][p], wq0.y, bb);
                        fma2(acc[2][p], wq1.x, bb);
                        fma2(acc[3][p], wq1.y, bb);
                    }
                }
            }
        }
        __syncthreads();                       // done reading cur buffers
        if (it + 1 < 128) COMMITIN(it + 1);    // fill in_s[(it+1)&1]
    }
    #undef PREFETCH
    #undef COMMITIN

    // SiLU + 1x1 conv partials
    float lp[7];
    #pragma unroll
    for (int p = 0; p < 7; p++) lp[p] = 0.f;
    #pragma unroll
    for (int j = 0; j < 4; j++) {
        int oca = oc0 + 2*j, ocb = oc0 + 2*j + 1;
        float ba = b1[oca], bb_ = b1[ocb];
        float wa = w2[oca], wb = w2[ocb];
        #pragma unroll
        for (int p = 0; p < 7; p++) {
            float2 v = unpack2(acc[j][p]);
            float ha = v.x + ba;
            float hb = v.y + bb_;
            lp[p] += wa * (ha / (1.f + expf(-ha)));
            lp[p] += wb * (hb / (1.f + expf(-hb)));
        }
    }
    #pragma unroll
    for (int p = 0; p < 7; p++) redbuf[ty][tx + 16*p] = lp[p];
    __syncthreads();
    if (tid < 112) {
        float s = b2[0];
        #pragma unroll
        for (int t = 0; t < 16; t++) s += redbuf[t][tid];
        int row = rt*4 + tid / 28, col = tid % 28;
        g_logit[r][row*28 + col] = s;   // sign(logit) == (sigmoid > 0.5)
    }
}

// =======================================================================
// K4: paste -> binary masks (float 0/1). grid (512 rows, 128 rois), 128 thr
// =======================================================================
__global__ void k4_paste(float* __restrict__ out)
{
    int r = blockIdx.y;
    int y = blockIdx.x;
    int tid = threadIdx.x;
    float4* dst = (float4*)(out + OFF_MASKS + (size_t)r*262144 + (size_t)y*512);

    __shared__ float brow[28];
    float4 v = make_float4(0.f, 0.f, 0.f, 0.f);
    int kp = g_keep[r];
    if (kp) {
        int x0 = g_bint[r][0], y0 = g_bint[r][1];
        int x1 = g_bint[r][2], y1 = g_bint[r][3];
        if (y >= y0 && y <= y1) {
            int h = y1 - y0 + 1, w = x1 - x0 + 1;
            int iy = min((y - y0) * 28 / h, 27);
            if (tid < 28) brow[tid] = (g_logit[r][iy*28 + tid] > 0.f) ? 1.f : 0.f;
            __syncthreads();
            float* vv = (float*)&v;
            #pragma unroll
            for (int q = 0; q < 4; q++) {
                int x = tid * 4 + q;
                if (x >= x0 && x <= x1) {
                    int ix = min((x - x0) * 28 / w, 27);
                    vv[q] = brow[ix];
                }
            }
        }
    }
    dst[tid] = v;
}

// =======================================================================
extern "C" void kernel_launch(void* const* d_in, const int* in_sizes, int n_in,
                              void* d_out, int out_size)
{
    const float* pred0 = (const float*)d_in[0];
    const float* pred1 = (const float*)d_in[1];
    const float* pred2 = (const float*)d_in[2];
    const float* pred3 = (const float*)d_in[3];
    const float* feat0 = (const float*)d_in[4];
    const float* feat1 = (const float*)d_in[5];
    const float* feat2 = (const float*)d_in[6];
    const float* feat3 = (const float*)d_in[7];
    const float* w1    = (const float*)d_in[8];
    const float* b1    = (const float*)d_in[9];
    const float* w2    = (const float*)d_in[10];
    const float* b2    = (const float*)d_in[11];
    float* out = (float*)d_out;
    (void)in_sizes; (void)n_in; (void)out_size;

    k0_wt    <<<1152, 256>>>(w1);
    k1_detect<<<1, 384>>>(pred0, pred1, pred2, pred3, out);
    k2_sample<<<dim3(8, NROI), 256>>>(feat0, feat1, feat2, feat3);
    k3_conv  <<<7 * NROI, 256>>>(b1, w2, b2);
    k4_paste <<<dim3(512, NROI), 128>>>(out);
}